// round 7
// baseline (speedup 1.0000x reference)
#include <cuda_runtime.h>
#include <math.h>
#include <stdint.h>

// Problem constants (fixed by setup_inputs)
#define B_  2
#define T_  2048
#define C_  1024
#define H_  16
#define D_  64
#define BT_ (B_*T_)          // 4096

// Scratch (allocation-free rule: __device__ globals)
__device__ float g_q[BT_*C_];
__device__ float g_k[BT_*C_];
__device__ float g_v[BT_*C_];
__device__ float g_attn[BT_*C_];
__device__ float g_xr[BT_*C_];      // tf32-rounded x
__device__ float g_wq[C_*C_];
__device__ float g_wk[C_*C_];
__device__ float g_wv[C_*C_];
__device__ float g_wo[C_*C_];

// ===========================================================================
// Helpers
// ===========================================================================
__device__ __forceinline__ uint32_t smem_u32(const void* p) {
    uint32_t a;
    asm("{ .reg .u64 t; cvta.to.shared.u64 t, %1; cvt.u32.u64 %0, t; }"
        : "=r"(a) : "l"(p));
    return a;
}
__device__ __forceinline__ void cp_async16(uint32_t saddr, const void* gaddr) {
    asm volatile("cp.async.ca.shared.global [%0], [%1], 16;"
                 :: "r"(saddr), "l"(gaddr) : "memory");
}
__device__ __forceinline__ void cp_commit() {
    asm volatile("cp.async.commit_group;" ::: "memory");
}
template<int N>
__device__ __forceinline__ void cp_wait() {
    asm volatile("cp.async.wait_group %0;" :: "n"(N) : "memory");
}
// tf32 mma: D = A(16x8) * B(8x8) + D   (row.col)
__device__ __forceinline__ void mma_tf32(float* c, const uint32_t* a, const uint32_t* b) {
    asm volatile(
        "mma.sync.aligned.m16n8k8.row.col.f32.tf32.tf32.f32 "
        "{%0,%1,%2,%3}, {%4,%5,%6,%7}, {%8,%9}, {%0,%1,%2,%3};"
        : "+f"(c[0]), "+f"(c[1]), "+f"(c[2]), "+f"(c[3])
        : "r"(a[0]), "r"(a[1]), "r"(a[2]), "r"(a[3]), "r"(b[0]), "r"(b[1]));
}
__device__ __forceinline__ float rtf32(float a) {
    float r;
    asm("cvt.rna.tf32.f32 %0, %1;" : "=f"(r) : "f"(a));
    return r;
}
__device__ __forceinline__ void split1(float x, uint32_t& hi, uint32_t& lo) {
    float h = rtf32(x);
    hi = __float_as_uint(h);
    lo = __float_as_uint(rtf32(x - h));
}

// ===========================================================================
// tf32 tensor-core GEMM (NT): C[m,n] = sum_k A[m,k] * W[n,k]
// CTA 128x128, K-chunk 32, 3-stage cp.async pipeline (loads run 2 chunks
// ahead), ONE barrier per chunk. 256 threads, warp tile 64x32, 4x4 m16n8k8.
// ===========================================================================
#define GK      32
#define GSTRIDE 36
#define G_TILE  (128 * GSTRIDE)
#define G_STAGE (2 * G_TILE)
#define G_SMEM  (3 * G_STAGE * (int)sizeof(float))   // 110592 B

__global__ __launch_bounds__(256, 2) void tf32_gemm(
    const float* __restrict__ A, const float* __restrict__ W,
    float* __restrict__ Cout, int M, int N, int K)
{
    extern __shared__ float sm[];
    const int tid  = threadIdx.x;
    const int lane = tid & 31;
    const int wid  = tid >> 5;
    const int wm   = wid >> 2;
    const int wn   = wid & 3;
    const int g    = lane >> 2;
    const int t    = lane & 3;
    const int row0 = blockIdx.y << 7;
    const int col0 = blockIdx.x << 7;

    float acc[4][4][4];
    #pragma unroll
    for (int i = 0; i < 4; ++i)
        #pragma unroll
        for (int j = 0; j < 4; ++j)
            #pragma unroll
            for (int r = 0; r < 4; ++r) acc[i][j][r] = 0.f;

    const int cr = tid >> 3;
    const int cc = (tid & 7) << 2;
    const int nchunk = K / GK;

    // prologue: chunks 0 and 1
    #pragma unroll
    for (int pc = 0; pc < 2; ++pc) {
        float* as = sm + pc * G_STAGE;
        float* bs = as + G_TILE;
        const int k0 = pc * GK;
        #pragma unroll
        for (int it = 0; it < 4; ++it) {
            int r = cr + (it << 5);
            cp_async16(smem_u32(as + r * GSTRIDE + cc),
                       A + (size_t)(row0 + r) * K + k0 + cc);
            cp_async16(smem_u32(bs + r * GSTRIDE + cc),
                       W + (size_t)(col0 + r) * K + k0 + cc);
        }
        cp_commit();
    }

    int buf = 0;                         // i % 3
    int nbuf = 2;                        // (i+2) % 3
    for (int i = 0; i < nchunk; ++i) {
        if (i + 1 < nchunk) cp_wait<1>(); else cp_wait<0>();
        __syncthreads();                 // chunk i visible; all done with i-1

        if (i + 2 < nchunk) {            // issue chunk i+2 (buffer of i-1)
            float* as = sm + nbuf * G_STAGE;
            float* bs = as + G_TILE;
            const int k0 = (i + 2) * GK;
            #pragma unroll
            for (int it = 0; it < 4; ++it) {
                int r = cr + (it << 5);
                cp_async16(smem_u32(as + r * GSTRIDE + cc),
                           A + (size_t)(row0 + r) * K + k0 + cc);
                cp_async16(smem_u32(bs + r * GSTRIDE + cc),
                           W + (size_t)(col0 + r) * K + k0 + cc);
            }
            cp_commit();
        }

        const float* as = sm + buf * G_STAGE + wm * 64 * GSTRIDE;
        const float* bs = sm + buf * G_STAGE + G_TILE + wn * 32 * GSTRIDE;

        #pragma unroll
        for (int ks = 0; ks < 4; ++ks) {
            uint32_t af[4][4];
            #pragma unroll
            for (int mt = 0; mt < 4; ++mt) {
                const uint32_t* ap =
                    (const uint32_t*)(as + (mt * 16 + g) * GSTRIDE + ks * 8 + t);
                af[mt][0] = ap[0];
                af[mt][1] = ap[8 * GSTRIDE];
                af[mt][2] = ap[4];
                af[mt][3] = ap[8 * GSTRIDE + 4];
            }
            uint32_t bf[4][2];
            #pragma unroll
            for (int nt = 0; nt < 4; ++nt) {
                const uint32_t* bp =
                    (const uint32_t*)(bs + (nt * 8 + g) * GSTRIDE + ks * 8 + t);
                bf[nt][0] = bp[0];
                bf[nt][1] = bp[4];
            }
            #pragma unroll
            for (int mt = 0; mt < 4; ++mt)
                #pragma unroll
                for (int nt = 0; nt < 4; ++nt)
                    mma_tf32(acc[mt][nt], af[mt], bf[nt]);
        }

        buf  = (buf  + 1 == 3) ? 0 : buf  + 1;
        nbuf = (nbuf + 1 == 3) ? 0 : nbuf + 1;
    }

    #pragma unroll
    for (int mt = 0; mt < 4; ++mt) {
        #pragma unroll
        for (int nt = 0; nt < 4; ++nt) {
            int row = row0 + wm * 64 + mt * 16 + g;
            int col = col0 + wn * 32 + nt * 8 + 2 * t;
            *(float2*)(Cout + (size_t)row * N + col) =
                make_float2(acc[mt][nt][0], acc[mt][nt][1]);
            *(float2*)(Cout + (size_t)(row + 8) * N + col) =
                make_float2(acc[mt][nt][2], acc[mt][nt][3]);
        }
    }
}

// ===========================================================================
// Fused rounding: x (1M float4) + 4 weights (256K float4 each), one launch
// ===========================================================================
#define N4X (BT_ * C_ / 4)       // 1048576
#define N4W (C_ * C_ / 4)        // 262144 = 2^18
__global__ void round_all_kernel(
    const float4* __restrict__ x,  float4* __restrict__ xr,
    const float4* __restrict__ wq, float4* __restrict__ oq,
    const float4* __restrict__ wk, float4* __restrict__ ok,
    const float4* __restrict__ wv, float4* __restrict__ ov,
    const float4* __restrict__ wo, float4* __restrict__ oo)
{
    int idx = blockIdx.x * blockDim.x + threadIdx.x;
    const float4* src; float4* dst; int off;
    if (idx < N4X) { src = x; dst = xr; off = idx; }
    else {
        int j = idx - N4X;
        int s = j >> 18;
        off = j & (N4W - 1);
        if      (s == 0) { src = wq; dst = oq; }
        else if (s == 1) { src = wk; dst = ok; }
        else if (s == 2) { src = wv; dst = ov; }
        else             { src = wo; dst = oo; }
    }
    float4 v = src[off];
    v.x = rtf32(v.x); v.y = rtf32(v.y); v.z = rtf32(v.z); v.w = rtf32(v.w);
    dst[off] = v;
}

// ---------------------------------------------------------------------------
// RoPE in-place on Q and K
// ---------------------------------------------------------------------------
__global__ void rope_kernel(float* __restrict__ q, float* __restrict__ k)
{
    int idx = blockIdx.x * blockDim.x + threadIdx.x;
    int i = idx & 31;
    int h = (idx >> 5) & 15;
    int t = (idx >> 9) & 2047;
    int b = idx >> 20;

    float inv = powf(10000.0f, -(float)(2 * i) / (float)D_);
    float ang = (float)t * inv;
    float s, c;
    sincosf(ang, &s, &c);

    size_t base = ((size_t)(b * T_ + t)) * C_ + h * D_ + i;
    float x1 = q[base], x2 = q[base + 32];
    q[base]      = x1 * c - x2 * s;
    q[base + 32] = x2 * c + x1 * s;
    x1 = k[base]; x2 = k[base + 32];
    k[base]      = x1 * c - x2 * s;
    k[base + 32] = x2 * c + x1 * s;
}

// ===========================================================================
// Tensor-core causal flash attention (tf32x3), R7:
//  - double-buffered K/V tiles via cp.async (load j+1 overlaps compute j)
//  - P stays in registers: accumulator->A-fragment remap via 8 shuffles/ks
//  - heavy query tiles launch first (reversed blockIdx.x)
// Tile: 128 queries x 64 keys, 256 threads, warp w owns 16 query rows.
// ===========================================================================
#define FQ   128
#define FK   64
#define QSTR 68
#define KSTR 68
#define VSTR 72
#define FA3_Q  0
#define FA3_K0 (FQ*QSTR)                          // 8704
#define FA3_V0 (FA3_K0 + 2*FK*KSTR)               // 8704 + 8704 = 17408
#define FA3_SMEM ((FA3_V0 + 2*FK*VSTR) * (int)sizeof(float))  // 106496 B

__global__ __launch_bounds__(256) void flash_attn_tc(
    const float* __restrict__ q, const float* __restrict__ k,
    const float* __restrict__ v, float* __restrict__ o)
{
    extern __shared__ float sm[];
    float* Qs = sm + FA3_Q;

    const int tid  = threadIdx.x;
    const int lane = tid & 31;
    const int w    = tid >> 5;
    const int g    = lane >> 2;
    const int t    = lane & 3;
    const int qb   = gridDim.x - 1 - blockIdx.x;   // heavy tiles first
    const int bh   = blockIdx.y;
    const int b    = bh >> 4, h = bh & 15;
    const int i0   = qb << 7;

    const float* qbp = q + (size_t)b * T_ * C_ + h * D_;
    const float* kbp = k + (size_t)b * T_ * C_ + h * D_;
    const float* vbp = v + (size_t)b * T_ * C_ + h * D_;

    const int njt = (i0 >> 6) + 2;          // causal key-tile count

    // prologue: Q tile + K/V tile 0 -> group 0
    #pragma unroll
    for (int it = 0; it < 8; ++it) {
        int task = tid + (it << 8);
        int r = task >> 4, c = (task & 15) << 2;
        cp_async16(smem_u32(Qs + r * QSTR + c),
                   qbp + (size_t)(i0 + r) * C_ + c);
    }
    {
        float* Ks = sm + FA3_K0;
        float* Vs = sm + FA3_V0;
        #pragma unroll
        for (int it = 0; it < 4; ++it) {
            int task = tid + (it << 8);
            int r = task >> 4, c = (task & 15) << 2;
            cp_async16(smem_u32(Ks + r * KSTR + c), kbp + (size_t)r * C_ + c);
            cp_async16(smem_u32(Vs + r * VSTR + c), vbp + (size_t)r * C_ + c);
        }
    }
    cp_commit();

    float oacc[8][4];
    #pragma unroll
    for (int nt = 0; nt < 8; ++nt)
        #pragma unroll
        for (int e = 0; e < 4; ++e) oacc[nt][e] = 0.f;
    float m0 = -1e30f, m1 = -1e30f, l0 = 0.f, l1 = 0.f;

    const int grow0 = i0 + w * 16 + g;
    const int srcA  = (g << 2) | (t >> 1);
    const int srcB  = srcA + 2;
    const bool odd  = (t & 1);

    for (int j = 0; j < njt; ++j) {
        cp_wait<0>();                       // tile j (and Q) resident
        __syncthreads();                    // visible; all done with j-1

        if (j + 1 < njt) {                  // prefetch tile j+1 (other buffer)
            float* Kn = sm + FA3_K0 + ((j + 1) & 1) * FK * KSTR;
            float* Vn = sm + FA3_V0 + ((j + 1) & 1) * FK * VSTR;
            const float* kb2 = kbp + (size_t)((j + 1) << 6) * C_;
            const float* vb2 = vbp + (size_t)((j + 1) << 6) * C_;
            #pragma unroll
            for (int it = 0; it < 4; ++it) {
                int task = tid + (it << 8);
                int r = task >> 4, c = (task & 15) << 2;
                cp_async16(smem_u32(Kn + r * KSTR + c), kb2 + (size_t)r * C_ + c);
                cp_async16(smem_u32(Vn + r * VSTR + c), vb2 + (size_t)r * C_ + c);
            }
            cp_commit();
        }

        const float* Ks = sm + FA3_K0 + (j & 1) * FK * KSTR;
        const float* Vs = sm + FA3_V0 + (j & 1) * FK * VSTR;

        // ---- S = Q K^T  (tf32x3) ----
        float sacc[8][4];
        #pragma unroll
        for (int nt = 0; nt < 8; ++nt)
            #pragma unroll
            for (int e = 0; e < 4; ++e) sacc[nt][e] = 0.f;

        const float* qrow = Qs + (w * 16 + g) * QSTR;
        #pragma unroll
        for (int ks = 0; ks < 8; ++ks) {
            uint32_t ah[4], al[4];
            split1(qrow[ks * 8 + t],            ah[0], al[0]);
            split1(qrow[8 * QSTR + ks * 8 + t], ah[1], al[1]);
            split1(qrow[ks * 8 + t + 4],            ah[2], al[2]);
            split1(qrow[8 * QSTR + ks * 8 + t + 4], ah[3], al[3]);
            #pragma unroll
            for (int nt = 0; nt < 8; ++nt) {
                const float* krow = Ks + (nt * 8 + g) * KSTR + ks * 8;
                uint32_t bh2[2], bl2[2];
                split1(krow[t],     bh2[0], bl2[0]);
                split1(krow[t + 4], bh2[1], bl2[1]);
                mma_tf32(sacc[nt], ah, bh2);
                mma_tf32(sacc[nt], ah, bl2);
                mma_tf32(sacc[nt], al, bh2);
            }
        }

        // ---- online softmax ----
        const int colj = j << 6;
        float mx0 = -1e30f, mx1 = -1e30f;
        #pragma unroll
        for (int nt = 0; nt < 8; ++nt) {
            #pragma unroll
            for (int e = 0; e < 4; ++e) {
                int gcol = colj + nt * 8 + 2 * t + (e & 1);
                int grow = (e < 2) ? grow0 : grow0 + 8;
                float val = sacc[nt][e] * 0.125f;
                if (gcol > grow) val = -1e30f;
                sacc[nt][e] = val;
            }
            mx0 = fmaxf(mx0, fmaxf(sacc[nt][0], sacc[nt][1]));
            mx1 = fmaxf(mx1, fmaxf(sacc[nt][2], sacc[nt][3]));
        }
        mx0 = fmaxf(mx0, __shfl_xor_sync(0xffffffffu, mx0, 1));
        mx0 = fmaxf(mx0, __shfl_xor_sync(0xffffffffu, mx0, 2));
        mx1 = fmaxf(mx1, __shfl_xor_sync(0xffffffffu, mx1, 1));
        mx1 = fmaxf(mx1, __shfl_xor_sync(0xffffffffu, mx1, 2));

        float mn0 = fmaxf(m0, mx0), mn1 = fmaxf(m1, mx1);
        float sc0 = __expf(m0 - mn0), sc1 = __expf(m1 - mn1);
        float rs0 = 0.f, rs1 = 0.f;
        #pragma unroll
        for (int nt = 0; nt < 8; ++nt) {
            float p0 = __expf(sacc[nt][0] - mn0);
            float p1 = __expf(sacc[nt][1] - mn0);
            float p2 = __expf(sacc[nt][2] - mn1);
            float p3 = __expf(sacc[nt][3] - mn1);
            sacc[nt][0] = p0; sacc[nt][1] = p1;
            sacc[nt][2] = p2; sacc[nt][3] = p3;
            rs0 += p0 + p1; rs1 += p2 + p3;
        }
        rs0 += __shfl_xor_sync(0xffffffffu, rs0, 1);
        rs0 += __shfl_xor_sync(0xffffffffu, rs0, 2);
        rs1 += __shfl_xor_sync(0xffffffffu, rs1, 1);
        rs1 += __shfl_xor_sync(0xffffffffu, rs1, 2);
        l0 = l0 * sc0 + rs0; m0 = mn0;
        l1 = l1 * sc1 + rs1; m1 = mn1;
        #pragma unroll
        for (int nt = 0; nt < 8; ++nt) {
            oacc[nt][0] *= sc0; oacc[nt][1] *= sc0;
            oacc[nt][2] *= sc1; oacc[nt][3] *= sc1;
        }

        // ---- O += P V  (tf32x3); P gathered from sacc via shuffles ----
        #pragma unroll
        for (int ks = 0; ks < 8; ++ks) {
            // A-fragment of P: rows (g, g+8), cols ks*8 + {t, t+4}
            float vA0 = __shfl_sync(0xffffffffu, sacc[ks][0], srcA);
            float vA1 = __shfl_sync(0xffffffffu, sacc[ks][1], srcA);
            float vA2 = __shfl_sync(0xffffffffu, sacc[ks][2], srcA);
            float vA3 = __shfl_sync(0xffffffffu, sacc[ks][3], srcA);
            float vB0 = __shfl_sync(0xffffffffu, sacc[ks][0], srcB);
            float vB1 = __shfl_sync(0xffffffffu, sacc[ks][1], srcB);
            float vB2 = __shfl_sync(0xffffffffu, sacc[ks][2], srcB);
            float vB3 = __shfl_sync(0xffffffffu, sacc[ks][3], srcB);
            float a0 = odd ? vA1 : vA0;     // (g,     ks*8+t)
            float a1 = odd ? vA3 : vA2;     // (g+8,   ks*8+t)
            float a2 = odd ? vB1 : vB0;     // (g,     ks*8+t+4)
            float a3 = odd ? vB3 : vB2;     // (g+8,   ks*8+t+4)
            uint32_t ah[4], al[4];
            split1(a0, ah[0], al[0]);
            split1(a1, ah[1], al[1]);
            split1(a2, ah[2], al[2]);
            split1(a3, ah[3], al[3]);
            #pragma unroll
            for (int nt = 0; nt < 8; ++nt) {
                uint32_t bh2[2], bl2[2];
                split1(Vs[(ks * 8 + t) * VSTR + nt * 8 + g],     bh2[0], bl2[0]);
                split1(Vs[(ks * 8 + t + 4) * VSTR + nt * 8 + g], bh2[1], bl2[1]);
                mma_tf32(oacc[nt], ah, bh2);
                mma_tf32(oacc[nt], ah, bl2);
                mma_tf32(oacc[nt], al, bh2);
            }
        }
    }

    // ---- epilogue (pre-rounded to tf32 for the Wo GEMM) ----
    float iv0 = 1.f / l0, iv1 = 1.f / l1;
    float* ob = o + (size_t)b * T_ * C_ + h * D_;
    #pragma unroll
    for (int nt = 0; nt < 8; ++nt) {
        int col = nt * 8 + 2 * t;
        *(float2*)(ob + (size_t)grow0 * C_ + col) =
            make_float2(rtf32(oacc[nt][0] * iv0), rtf32(oacc[nt][1] * iv0));
        *(float2*)(ob + (size_t)(grow0 + 8) * C_ + col) =
            make_float2(rtf32(oacc[nt][2] * iv1), rtf32(oacc[nt][3] * iv1));
    }
}

// ---------------------------------------------------------------------------
// Launch
// ---------------------------------------------------------------------------
extern "C" void kernel_launch(void* const* d_in, const int* in_sizes, int n_in,
                              void* d_out, int out_size)
{
    const float* x  = (const float*)d_in[0];
    const float* Wq = (const float*)d_in[1];
    const float* Wk = (const float*)d_in[2];
    const float* Wv = (const float*)d_in[3];
    const float* Wo = (const float*)d_in[4];
    float* out = (float*)d_out;

    float *qp, *kp, *vp, *ap, *xr, *wq, *wk, *wv, *wo;
    cudaGetSymbolAddress((void**)&qp, g_q);
    cudaGetSymbolAddress((void**)&kp, g_k);
    cudaGetSymbolAddress((void**)&vp, g_v);
    cudaGetSymbolAddress((void**)&ap, g_attn);
    cudaGetSymbolAddress((void**)&xr, g_xr);
    cudaGetSymbolAddress((void**)&wq, g_wq);
    cudaGetSymbolAddress((void**)&wk, g_wk);
    cudaGetSymbolAddress((void**)&wv, g_wv);
    cudaGetSymbolAddress((void**)&wo, g_wo);

    cudaFuncSetAttribute((const void*)tf32_gemm,
                         cudaFuncAttributeMaxDynamicSharedMemorySize, G_SMEM);
    cudaFuncSetAttribute((const void*)flash_attn_tc,
                         cudaFuncAttributeMaxDynamicSharedMemorySize, FA3_SMEM);

    // One fused rounding pass over x + all four weights
    round_all_kernel<<<(N4X + 4 * N4W) / 256, 256>>>(
        (const float4*)x,  (float4*)xr,
        (const float4*)Wq, (float4*)wq,
        (const float4*)Wk, (float4*)wk,
        (const float4*)Wv, (float4*)wv,
        (const float4*)Wo, (float4*)wo);

    dim3 gg(C_ / 128, BT_ / 128);   // (8, 32)
    tf32_gemm<<<gg, 256, G_SMEM>>>(xr, wq, qp, BT_, C_, C_);
    tf32_gemm<<<gg, 256, G_SMEM>>>(xr, wk, kp, BT_, C_, C_);
    tf32_gemm<<<gg, 256, G_SMEM>>>(xr, wv, vp, BT_, C_, C_);

    rope_kernel<<<(B_ * T_ * H_ * (D_ / 2)) / 256, 256>>>(qp, kp);

    flash_attn_tc<<<dim3(T_ / 128, B_ * H_), 256, FA3_SMEM>>>(qp, kp, vp, ap);

    tf32_gemm<<<gg, 256, G_SMEM>>>(ap, wo, out, BT_, C_, C_);
}

// round 8
// speedup vs baseline: 1.0113x; 1.0113x over previous
#include <cuda_runtime.h>
#include <math.h>
#include <stdint.h>

// Problem constants (fixed by setup_inputs)
#define B_  2
#define T_  2048
#define C_  1024
#define H_  16
#define D_  64
#define BT_ (B_*T_)          // 4096

// Scratch (allocation-free rule: __device__ globals)
__device__ float g_q[BT_*C_];
__device__ float g_k[BT_*C_];
__device__ float g_v[BT_*C_];
__device__ float g_attn[BT_*C_];
__device__ float g_xr[BT_*C_];      // tf32-rounded x
__device__ float g_wq[C_*C_];
__device__ float g_wk[C_*C_];
__device__ float g_wv[C_*C_];
__device__ float g_wo[C_*C_];

// ===========================================================================
// Helpers
// ===========================================================================
__device__ __forceinline__ uint32_t smem_u32(const void* p) {
    uint32_t a;
    asm("{ .reg .u64 t; cvta.to.shared.u64 t, %1; cvt.u32.u64 %0, t; }"
        : "=r"(a) : "l"(p));
    return a;
}
__device__ __forceinline__ void cp_async16(uint32_t saddr, const void* gaddr) {
    asm volatile("cp.async.ca.shared.global [%0], [%1], 16;"
                 :: "r"(saddr), "l"(gaddr) : "memory");
}
__device__ __forceinline__ void cp_commit() {
    asm volatile("cp.async.commit_group;" ::: "memory");
}
template<int N>
__device__ __forceinline__ void cp_wait() {
    asm volatile("cp.async.wait_group %0;" :: "n"(N) : "memory");
}
// tf32 mma: D = A(16x8) * B(8x8) + D   (row.col)
__device__ __forceinline__ void mma_tf32(float* c, const uint32_t* a, const uint32_t* b) {
    asm volatile(
        "mma.sync.aligned.m16n8k8.row.col.f32.tf32.tf32.f32 "
        "{%0,%1,%2,%3}, {%4,%5,%6,%7}, {%8,%9}, {%0,%1,%2,%3};"
        : "+f"(c[0]), "+f"(c[1]), "+f"(c[2]), "+f"(c[3])
        : "r"(a[0]), "r"(a[1]), "r"(a[2]), "r"(a[3]), "r"(b[0]), "r"(b[1]));
}
__device__ __forceinline__ float rtf32(float a) {
    float r;
    asm("cvt.rna.tf32.f32 %0, %1;" : "=f"(r) : "f"(a));
    return r;
}
__device__ __forceinline__ void split1(float x, uint32_t& hi, uint32_t& lo) {
    float h = rtf32(x);
    hi = __float_as_uint(h);
    lo = __float_as_uint(rtf32(x - h));
}

// ===========================================================================
// tf32 tensor-core GEMM (NT): C[m,n] = sum_k A[m,k] * W[n,k]
// CTA 128x128, K-chunk 32, 3-stage cp.async pipeline (loads run 2 chunks
// ahead), ONE barrier per chunk. 256 threads, warp tile 64x32, 4x4 m16n8k8.
// (validated R7: 73.4us, tensor=37.4%)
// ===========================================================================
#define GK      32
#define GSTRIDE 36
#define G_TILE  (128 * GSTRIDE)
#define G_STAGE (2 * G_TILE)
#define G_SMEM  (3 * G_STAGE * (int)sizeof(float))   // 110592 B

__global__ __launch_bounds__(256, 2) void tf32_gemm(
    const float* __restrict__ A, const float* __restrict__ W,
    float* __restrict__ Cout, int M, int N, int K)
{
    extern __shared__ float sm[];
    const int tid  = threadIdx.x;
    const int lane = tid & 31;
    const int wid  = tid >> 5;
    const int wm   = wid >> 2;
    const int wn   = wid & 3;
    const int g    = lane >> 2;
    const int t    = lane & 3;
    const int row0 = blockIdx.y << 7;
    const int col0 = blockIdx.x << 7;

    float acc[4][4][4];
    #pragma unroll
    for (int i = 0; i < 4; ++i)
        #pragma unroll
        for (int j = 0; j < 4; ++j)
            #pragma unroll
            for (int r = 0; r < 4; ++r) acc[i][j][r] = 0.f;

    const int cr = tid >> 3;
    const int cc = (tid & 7) << 2;
    const int nchunk = K / GK;

    // prologue: chunks 0 and 1
    #pragma unroll
    for (int pc = 0; pc < 2; ++pc) {
        float* as = sm + pc * G_STAGE;
        float* bs = as + G_TILE;
        const int k0 = pc * GK;
        #pragma unroll
        for (int it = 0; it < 4; ++it) {
            int r = cr + (it << 5);
            cp_async16(smem_u32(as + r * GSTRIDE + cc),
                       A + (size_t)(row0 + r) * K + k0 + cc);
            cp_async16(smem_u32(bs + r * GSTRIDE + cc),
                       W + (size_t)(col0 + r) * K + k0 + cc);
        }
        cp_commit();
    }

    int buf = 0;
    int nbuf = 2;
    for (int i = 0; i < nchunk; ++i) {
        if (i + 1 < nchunk) cp_wait<1>(); else cp_wait<0>();
        __syncthreads();

        if (i + 2 < nchunk) {
            float* as = sm + nbuf * G_STAGE;
            float* bs = as + G_TILE;
            const int k0 = (i + 2) * GK;
            #pragma unroll
            for (int it = 0; it < 4; ++it) {
                int r = cr + (it << 5);
                cp_async16(smem_u32(as + r * GSTRIDE + cc),
                           A + (size_t)(row0 + r) * K + k0 + cc);
                cp_async16(smem_u32(bs + r * GSTRIDE + cc),
                           W + (size_t)(col0 + r) * K + k0 + cc);
            }
            cp_commit();
        }

        const float* as = sm + buf * G_STAGE + wm * 64 * GSTRIDE;
        const float* bs = sm + buf * G_STAGE + G_TILE + wn * 32 * GSTRIDE;

        #pragma unroll
        for (int ks = 0; ks < 4; ++ks) {
            uint32_t af[4][4];
            #pragma unroll
            for (int mt = 0; mt < 4; ++mt) {
                const uint32_t* ap =
                    (const uint32_t*)(as + (mt * 16 + g) * GSTRIDE + ks * 8 + t);
                af[mt][0] = ap[0];
                af[mt][1] = ap[8 * GSTRIDE];
                af[mt][2] = ap[4];
                af[mt][3] = ap[8 * GSTRIDE + 4];
            }
            uint32_t bf[4][2];
            #pragma unroll
            for (int nt = 0; nt < 4; ++nt) {
                const uint32_t* bp =
                    (const uint32_t*)(bs + (nt * 8 + g) * GSTRIDE + ks * 8 + t);
                bf[nt][0] = bp[0];
                bf[nt][1] = bp[4];
            }
            #pragma unroll
            for (int mt = 0; mt < 4; ++mt)
                #pragma unroll
                for (int nt = 0; nt < 4; ++nt)
                    mma_tf32(acc[mt][nt], af[mt], bf[nt]);
        }

        buf  = (buf  + 1 == 3) ? 0 : buf  + 1;
        nbuf = (nbuf + 1 == 3) ? 0 : nbuf + 1;
    }

    #pragma unroll
    for (int mt = 0; mt < 4; ++mt) {
        #pragma unroll
        for (int nt = 0; nt < 4; ++nt) {
            int row = row0 + wm * 64 + mt * 16 + g;
            int col = col0 + wn * 32 + nt * 8 + 2 * t;
            *(float2*)(Cout + (size_t)row * N + col) =
                make_float2(acc[mt][nt][0], acc[mt][nt][1]);
            *(float2*)(Cout + (size_t)(row + 8) * N + col) =
                make_float2(acc[mt][nt][2], acc[mt][nt][3]);
        }
    }
}

// ===========================================================================
// Fused rounding: x (1M float4) + 4 weights (256K float4 each), one launch
// ===========================================================================
#define N4X (BT_ * C_ / 4)       // 1048576
#define N4W (C_ * C_ / 4)        // 262144 = 2^18
__global__ void round_all_kernel(
    const float4* __restrict__ x,  float4* __restrict__ xr,
    const float4* __restrict__ wq, float4* __restrict__ oq,
    const float4* __restrict__ wk, float4* __restrict__ ok,
    const float4* __restrict__ wv, float4* __restrict__ ov,
    const float4* __restrict__ wo, float4* __restrict__ oo)
{
    int idx = blockIdx.x * blockDim.x + threadIdx.x;
    const float4* src; float4* dst; int off;
    if (idx < N4X) { src = x; dst = xr; off = idx; }
    else {
        int j = idx - N4X;
        int s = j >> 18;
        off = j & (N4W - 1);
        if      (s == 0) { src = wq; dst = oq; }
        else if (s == 1) { src = wk; dst = ok; }
        else if (s == 2) { src = wv; dst = ov; }
        else             { src = wo; dst = oo; }
    }
    float4 v = src[off];
    v.x = rtf32(v.x); v.y = rtf32(v.y); v.z = rtf32(v.z); v.w = rtf32(v.w);
    dst[off] = v;
}

// ---------------------------------------------------------------------------
// RoPE in-place on Q and K
// ---------------------------------------------------------------------------
__global__ void rope_kernel(float* __restrict__ q, float* __restrict__ k)
{
    int idx = blockIdx.x * blockDim.x + threadIdx.x;
    int i = idx & 31;
    int h = (idx >> 5) & 15;
    int t = (idx >> 9) & 2047;
    int b = idx >> 20;

    float inv = powf(10000.0f, -(float)(2 * i) / (float)D_);
    float ang = (float)t * inv;
    float s, c;
    sincosf(ang, &s, &c);

    size_t base = ((size_t)(b * T_ + t)) * C_ + h * D_ + i;
    float x1 = q[base], x2 = q[base + 32];
    q[base]      = x1 * c - x2 * s;
    q[base + 32] = x2 * c + x1 * s;
    x1 = k[base]; x2 = k[base + 32];
    k[base]      = x1 * c - x2 * s;
    k[base + 32] = x2 * c + x1 * s;
}

// ===========================================================================
// Tensor-core causal flash attention (tf32x3) — exact R6 configuration
// (measured inside the 826.5us run): smem P tile, single K/V buffer,
// natural qb order. Tile 128 queries x 64 keys, 256 threads.
// ===========================================================================
#define FQ   128
#define FK   64
#define QSTR 68
#define KSTR 68
#define VSTR 72
#define PSTR 68
#define FA2_Q 0
#define FA2_K (FQ*QSTR)                       // 8704
#define FA2_V (FA2_K + FK*KSTR)               // 13056
#define FA2_P (FA2_V + FK*VSTR)               // 17664
#define FA2_SMEM ((FA2_P + FQ*PSTR) * (int)sizeof(float))   // 105472 B

__global__ __launch_bounds__(256) void flash_attn_tc(
    const float* __restrict__ q, const float* __restrict__ k,
    const float* __restrict__ v, float* __restrict__ o)
{
    extern __shared__ float sm[];
    float* Qs = sm + FA2_Q;
    float* Ks = sm + FA2_K;
    float* Vs = sm + FA2_V;
    float* Ps = sm + FA2_P;

    const int tid  = threadIdx.x;
    const int lane = tid & 31;
    const int w    = tid >> 5;
    const int g    = lane >> 2;
    const int t    = lane & 3;
    const int qb   = blockIdx.x;
    const int bh   = blockIdx.y;
    const int b    = bh >> 4, h = bh & 15;
    const int i0   = qb << 7;

    const float* qbp = q + (size_t)b * T_ * C_ + h * D_;
    const float* kbp = k + (size_t)b * T_ * C_ + h * D_;
    const float* vbp = v + (size_t)b * T_ * C_ + h * D_;

    // Load Q tile (128 x 64) via cp.async
    #pragma unroll
    for (int it = 0; it < 8; ++it) {
        int task = tid + (it << 8);
        int r = task >> 4, c = (task & 15) << 2;
        cp_async16(smem_u32(Qs + r * QSTR + c),
                   qbp + (size_t)(i0 + r) * C_ + c);
    }
    cp_commit();

    float oacc[8][4];
    #pragma unroll
    for (int nt = 0; nt < 8; ++nt)
        #pragma unroll
        for (int e = 0; e < 4; ++e) oacc[nt][e] = 0.f;
    float m0 = -1e30f, m1 = -1e30f, l0 = 0.f, l1 = 0.f;

    const int grow0 = i0 + w * 16 + g;
    const int njt = (i0 >> 6) + 2;          // causal key-tile count

    for (int j = 0; j < njt; ++j) {
        __syncthreads();                    // prev iter done reading K/V
        #pragma unroll
        for (int it = 0; it < 4; ++it) {
            int task = tid + (it << 8);
            int r = task >> 4, c = (task & 15) << 2;
            cp_async16(smem_u32(Ks + r * KSTR + c),
                       kbp + (size_t)((j << 6) + r) * C_ + c);
            cp_async16(smem_u32(Vs + r * VSTR + c),
                       vbp + (size_t)((j << 6) + r) * C_ + c);
        }
        cp_commit();
        cp_wait<0>();
        __syncthreads();

        // ---- S = Q K^T  (tf32x3) ----
        float sacc[8][4];
        #pragma unroll
        for (int nt = 0; nt < 8; ++nt)
            #pragma unroll
            for (int e = 0; e < 4; ++e) sacc[nt][e] = 0.f;

        const float* qrow = Qs + (w * 16 + g) * QSTR;
        #pragma unroll
        for (int ks = 0; ks < 8; ++ks) {
            uint32_t ah[4], al[4];
            split1(qrow[ks * 8 + t],            ah[0], al[0]);
            split1(qrow[8 * QSTR + ks * 8 + t], ah[1], al[1]);
            split1(qrow[ks * 8 + t + 4],            ah[2], al[2]);
            split1(qrow[8 * QSTR + ks * 8 + t + 4], ah[3], al[3]);
            #pragma unroll
            for (int nt = 0; nt < 8; ++nt) {
                const float* krow = Ks + (nt * 8 + g) * KSTR + ks * 8;
                uint32_t bh2[2], bl2[2];
                split1(krow[t],     bh2[0], bl2[0]);
                split1(krow[t + 4], bh2[1], bl2[1]);
                mma_tf32(sacc[nt], ah, bh2);
                mma_tf32(sacc[nt], ah, bl2);
                mma_tf32(sacc[nt], al, bh2);
            }
        }

        // ---- online softmax ----
        const int colj = j << 6;
        float mx0 = -1e30f, mx1 = -1e30f;
        #pragma unroll
        for (int nt = 0; nt < 8; ++nt) {
            #pragma unroll
            for (int e = 0; e < 4; ++e) {
                int gcol = colj + nt * 8 + 2 * t + (e & 1);
                int grow = (e < 2) ? grow0 : grow0 + 8;
                float val = sacc[nt][e] * 0.125f;
                if (gcol > grow) val = -1e30f;
                sacc[nt][e] = val;
            }
            mx0 = fmaxf(mx0, fmaxf(sacc[nt][0], sacc[nt][1]));
            mx1 = fmaxf(mx1, fmaxf(sacc[nt][2], sacc[nt][3]));
        }
        mx0 = fmaxf(mx0, __shfl_xor_sync(0xffffffffu, mx0, 1));
        mx0 = fmaxf(mx0, __shfl_xor_sync(0xffffffffu, mx0, 2));
        mx1 = fmaxf(mx1, __shfl_xor_sync(0xffffffffu, mx1, 1));
        mx1 = fmaxf(mx1, __shfl_xor_sync(0xffffffffu, mx1, 2));

        float mn0 = fmaxf(m0, mx0), mn1 = fmaxf(m1, mx1);
        float sc0 = __expf(m0 - mn0), sc1 = __expf(m1 - mn1);
        float rs0 = 0.f, rs1 = 0.f;
        #pragma unroll
        for (int nt = 0; nt < 8; ++nt) {
            float p0 = __expf(sacc[nt][0] - mn0);
            float p1 = __expf(sacc[nt][1] - mn0);
            float p2 = __expf(sacc[nt][2] - mn1);
            float p3 = __expf(sacc[nt][3] - mn1);
            sacc[nt][0] = p0; sacc[nt][1] = p1;
            sacc[nt][2] = p2; sacc[nt][3] = p3;
            rs0 += p0 + p1; rs1 += p2 + p3;
        }
        rs0 += __shfl_xor_sync(0xffffffffu, rs0, 1);
        rs0 += __shfl_xor_sync(0xffffffffu, rs0, 2);
        rs1 += __shfl_xor_sync(0xffffffffu, rs1, 1);
        rs1 += __shfl_xor_sync(0xffffffffu, rs1, 2);
        l0 = l0 * sc0 + rs0; m0 = mn0;
        l1 = l1 * sc1 + rs1; m1 = mn1;
        #pragma unroll
        for (int nt = 0; nt < 8; ++nt) {
            oacc[nt][0] *= sc0; oacc[nt][1] *= sc0;
            oacc[nt][2] *= sc1; oacc[nt][3] *= sc1;
        }

        // ---- write P (warp-private rows) ----
        __syncwarp();
        float* prow = Ps + (w * 16 + g) * PSTR;
        #pragma unroll
        for (int nt = 0; nt < 8; ++nt) {
            *(float2*)(prow + nt * 8 + 2 * t) =
                make_float2(sacc[nt][0], sacc[nt][1]);
            *(float2*)(prow + 8 * PSTR + nt * 8 + 2 * t) =
                make_float2(sacc[nt][2], sacc[nt][3]);
        }
        __syncwarp();

        // ---- O += P V  (tf32x3) ----
        #pragma unroll
        for (int ks = 0; ks < 8; ++ks) {
            uint32_t ah[4], al[4];
            split1(prow[ks * 8 + t],            ah[0], al[0]);
            split1(prow[8 * PSTR + ks * 8 + t], ah[1], al[1]);
            split1(prow[ks * 8 + t + 4],            ah[2], al[2]);
            split1(prow[8 * PSTR + ks * 8 + t + 4], ah[3], al[3]);
            #pragma unroll
            for (int nt = 0; nt < 8; ++nt) {
                uint32_t bh2[2], bl2[2];
                split1(Vs[(ks * 8 + t) * VSTR + nt * 8 + g],     bh2[0], bl2[0]);
                split1(Vs[(ks * 8 + t + 4) * VSTR + nt * 8 + g], bh2[1], bl2[1]);
                mma_tf32(oacc[nt], ah, bh2);
                mma_tf32(oacc[nt], ah, bl2);
                mma_tf32(oacc[nt], al, bh2);
            }
        }
    }

    // ---- epilogue (pre-rounded to tf32 for the Wo GEMM) ----
    float iv0 = 1.f / l0, iv1 = 1.f / l1;
    float* ob = o + (size_t)b * T_ * C_ + h * D_;
    #pragma unroll
    for (int nt = 0; nt < 8; ++nt) {
        int col = nt * 8 + 2 * t;
        *(float2*)(ob + (size_t)grow0 * C_ + col) =
            make_float2(rtf32(oacc[nt][0] * iv0), rtf32(oacc[nt][1] * iv0));
        *(float2*)(ob + (size_t)(grow0 + 8) * C_ + col) =
            make_float2(rtf32(oacc[nt][2] * iv1), rtf32(oacc[nt][3] * iv1));
    }
}

// ---------------------------------------------------------------------------
// Launch
// ---------------------------------------------------------------------------
extern "C" void kernel_launch(void* const* d_in, const int* in_sizes, int n_in,
                              void* d_out, int out_size)
{
    const float* x  = (const float*)d_in[0];
    const float* Wq = (const float*)d_in[1];
    const float* Wk = (const float*)d_in[2];
    const float* Wv = (const float*)d_in[3];
    const float* Wo = (const float*)d_in[4];
    float* out = (float*)d_out;

    float *qp, *kp, *vp, *ap, *xr, *wq, *wk, *wv, *wo;
    cudaGetSymbolAddress((void**)&qp, g_q);
    cudaGetSymbolAddress((void**)&kp, g_k);
    cudaGetSymbolAddress((void**)&vp, g_v);
    cudaGetSymbolAddress((void**)&ap, g_attn);
    cudaGetSymbolAddress((void**)&xr, g_xr);
    cudaGetSymbolAddress((void**)&wq, g_wq);
    cudaGetSymbolAddress((void**)&wk, g_wk);
    cudaGetSymbolAddress((void**)&wv, g_wv);
    cudaGetSymbolAddress((void**)&wo, g_wo);

    cudaFuncSetAttribute((const void*)tf32_gemm,
                         cudaFuncAttributeMaxDynamicSharedMemorySize, G_SMEM);
    cudaFuncSetAttribute((const void*)flash_attn_tc,
                         cudaFuncAttributeMaxDynamicSharedMemorySize, FA2_SMEM);

    // One fused rounding pass over x + all four weights
    round_all_kernel<<<(N4X + 4 * N4W) / 256, 256>>>(
        (const float4*)x,  (float4*)xr,
        (const float4*)Wq, (float4*)wq,
        (const float4*)Wk, (float4*)wk,
        (const float4*)Wv, (float4*)wv,
        (const float4*)Wo, (float4*)wo);

    dim3 gg(C_ / 128, BT_ / 128);   // (8, 32)
    tf32_gemm<<<gg, 256, G_SMEM>>>(xr, wq, qp, BT_, C_, C_);
    tf32_gemm<<<gg, 256, G_SMEM>>>(xr, wk, kp, BT_, C_, C_);
    tf32_gemm<<<gg, 256, G_SMEM>>>(xr, wv, vp, BT_, C_, C_);

    rope_kernel<<<(B_ * T_ * H_ * (D_ / 2)) / 256, 256>>>(qp, kp);

    flash_attn_tc<<<dim3(T_ / 128, B_ * H_), 256, FA2_SMEM>>>(qp, kp, vp, ap);

    tf32_gemm<<<gg, 256, G_SMEM>>>(ap, wo, out, BT_, C_, C_);
}